// round 14
// baseline (speedup 1.0000x reference)
#include <cuda_runtime.h>

// LSTM, batch=1, H=4, T=2^20, float32.
// Chunked time-parallel scan exploiting exponential state contraction.
// R13 = R12 smem staging + alignment-clean FFMA2 math.
//   Diagnosis: the 3-reg FFMA pipe (rt_SMSP=2) is ~80% occupied — the wall.
//   Fix: K-paired f32x2 accumulation with zero repacking:
//     - x read from smem as double2 (LDS.128 -> two aligned u64 K-pairs, free)
//     - u64 accumulators end-to-end: 16 FFMA2 + 4 FADD vs 32 FFMA
//     - h-exchange: 3 scalar SHFL.BFLY + 2 packs (only remaining MOVs)
//   i/f/o rows prescaled by 0.5 (sigmoid = MUFU.TANH + FFMA).
// CL=32, WU=32, 131072 threads / 4096 warps / 1024 blocks of 128.

#define T_LEN   1048576
#define CL      32
#define WU      32
#define NCHUNK  (T_LEN / CL)        // 32768
#define NTHREADS (NCHUNK * 4)       // 131072
#define BLOCK   128
#define CPB     (BLOCK / 4)         // 32 chunks per block
#define WIN     (CPB * CL + WU + CL)// 1056 timesteps per block window
#define XSLOTS  (WIN + WIN / 32 + 2)

typedef unsigned long long u64;

__device__ __forceinline__ float tanh_mufu(float z) {
    float r;
    asm("tanh.approx.f32 %0, %1;" : "=f"(r) : "f"(z));
    return r;
}
__device__ __forceinline__ float shfl_bfly4_1(float v) {
    float r;
    asm("shfl.sync.bfly.b32 %0, %1, 1, 0x1c1f, 0xffffffff;" : "=f"(r) : "f"(v));
    return r;
}
__device__ __forceinline__ float shfl_bfly4_2(float v) {
    float r;
    asm("shfl.sync.bfly.b32 %0, %1, 2, 0x1c1f, 0xffffffff;" : "=f"(r) : "f"(v));
    return r;
}
__device__ __forceinline__ float shfl_bfly4_3(float v) {
    float r;
    asm("shfl.sync.bfly.b32 %0, %1, 3, 0x1c1f, 0xffffffff;" : "=f"(r) : "f"(v));
    return r;
}
__device__ __forceinline__ u64 pack2(float lo, float hi) {
    u64 r; asm("mov.b64 %0, {%1, %2};" : "=l"(r) : "f"(lo), "f"(hi)); return r;
}
__device__ __forceinline__ void unpack2(u64 p, float& lo, float& hi) {
    asm("mov.b64 {%0, %1}, %2;" : "=f"(lo), "=f"(hi) : "l"(p));
}
__device__ __forceinline__ u64 fma2(u64 a, u64 b, u64 c) {
    u64 r; asm("fma.rn.f32x2 %0, %1, %2, %3;" : "=l"(r) : "l"(a), "l"(b), "l"(c)); return r;
}

__global__ void __launch_bounds__(BLOCK, 7)
lstm_chunked_scan(const float4* __restrict__ x,      // [T] of float4 (H=4)
                  const float*  __restrict__ Wih,    // [16][4]
                  const float*  __restrict__ Whh,    // [16][4]
                  const float*  __restrict__ bih,    // [16]
                  const float*  __restrict__ bhh,    // [16]
                  const float*  __restrict__ h0v,    // [4]
                  const float*  __restrict__ c0v,    // [4]
                  float*        __restrict__ out)    // [T][4]
{
    __shared__ double2 xs[XSLOTS];                   // 16B slots: {x0,x1},{x2,x3}

    const int c = threadIdx.x >> 2;                  // chunk within block
    const int j = threadIdx.x & 3;                   // output element
    const int g = blockIdx.x * CPB + c;              // global chunk id

    // ---- preload the block's x window (clamped, coalesced) ----
    const int t_base = blockIdx.x * (CPB * CL) - WU;
    const double2* xg = (const double2*)x;
    #pragma unroll 1
    for (int i = threadIdx.x; i < WIN; i += BLOCK) {
        int t = t_base + i;
        t = t < 0 ? 0 : (t >= T_LEN ? T_LEN - 1 : t);
        xs[i + (i >> 5)] = __ldg(&xg[t]);            // skew: +1 slot per 32
    }

    // K-paired per-lane weights. m: 0=i 1=f 2=g 3=o, row r=j+4m.
    // i/f/o rows prescaled by 0.5. wh01[m] = {Whh[r][j], Whh[r][j^1]},
    // wh23[m] = {Whh[r][j^2], Whh[r][j^3]} (butterfly-permuted columns).
    u64 wx01[4], wx23[4], wh01[4], wh23[4], bz[4];
    #pragma unroll
    for (int m = 0; m < 4; m++) {
        const int r = j + 4 * m;
        const float sc = (m == 2) ? 1.0f : 0.5f;
        wx01[m] = pack2(sc * __ldg(&Wih[r * 4 + 0]), sc * __ldg(&Wih[r * 4 + 1]));
        wx23[m] = pack2(sc * __ldg(&Wih[r * 4 + 2]), sc * __ldg(&Wih[r * 4 + 3]));
        wh01[m] = pack2(sc * __ldg(&Whh[r * 4 + (j ^ 0)]), sc * __ldg(&Whh[r * 4 + (j ^ 1)]));
        wh23[m] = pack2(sc * __ldg(&Whh[r * 4 + (j ^ 2)]), sc * __ldg(&Whh[r * 4 + (j ^ 3)]));
        bz[m]   = pack2(sc * (__ldg(&bih[r]) + __ldg(&bhh[r])), 0.0f);
    }

    float h  = __ldg(&h0v[j]);
    float c_ = __ldg(&c0v[j]);

    __syncthreads();

    // chunk c's window: warmup step s -> slot 33c + s; emission gets +1 skew
    const double2* xw = &xs[33 * c];

    // One LSTM step. Gate m accumulates as u64 {even-K sum, odd-K sum}:
    //   a_m = {b + w0 x0 + w2 x2 + wh0 h_j     + wh2 h_{j^2},
    //              w1 x1 + w3 x3 + wh1 h_{j^1} + wh3 h_{j^3}},  z_m = lo+hi
#define STEP(XD, CN, HN)                                                  \
    const float v1 = shfl_bfly4_1(h);                                     \
    const float v2 = shfl_bfly4_2(h);                                     \
    const float v3 = shfl_bfly4_3(h);                                     \
    const u64 xl = __double_as_longlong((XD).x);                          \
    const u64 xh = __double_as_longlong((XD).y);                          \
    const u64 hlo = pack2(h, v1);                                         \
    const u64 hhi = pack2(v2, v3);                                        \
    u64 a0 = fma2(wx01[0], xl, bz[0]);                                    \
    u64 a1 = fma2(wx01[1], xl, bz[1]);                                    \
    u64 a2 = fma2(wx01[2], xl, bz[2]);                                    \
    u64 a3 = fma2(wx01[3], xl, bz[3]);                                    \
    a0 = fma2(wx23[0], xh, a0);  a1 = fma2(wx23[1], xh, a1);              \
    a2 = fma2(wx23[2], xh, a2);  a3 = fma2(wx23[3], xh, a3);              \
    a0 = fma2(wh01[0], hlo, a0); a1 = fma2(wh01[1], hlo, a1);             \
    a2 = fma2(wh01[2], hlo, a2); a3 = fma2(wh01[3], hlo, a3);             \
    a0 = fma2(wh23[0], hhi, a0); a1 = fma2(wh23[1], hhi, a1);             \
    a2 = fma2(wh23[2], hhi, a2); a3 = fma2(wh23[3], hhi, a3);             \
    float zl0, zh0, zl1, zh1, zl2, zh2, zl3, zh3;                         \
    unpack2(a0, zl0, zh0); unpack2(a1, zl1, zh1);                         \
    unpack2(a2, zl2, zh2); unpack2(a3, zl3, zh3);                         \
    const float ig = fmaf(0.5f, tanh_mufu(zl0 + zh0), 0.5f);              \
    const float fg = fmaf(0.5f, tanh_mufu(zl1 + zh1), 0.5f);              \
    const float gv = tanh_mufu(zl2 + zh2);                                \
    const float og = fmaf(0.5f, tanh_mufu(zl3 + zh3), 0.5f);              \
    const float CN = fmaf(fg, c_, ig * gv);                               \
    const float HN = og * tanh_mufu(CN)

    // ---- warmup (no stores) ----
    if (blockIdx.x == 0) {
        const int t0 = g * CL - WU;
        #pragma unroll 4
        for (int s = 0; s < WU; ++s) {
            const double2 xd = xw[s];
            STEP(xd, cn, hn);
            const bool live = (t0 + s >= 0);
            c_ = live ? cn : c_;
            h  = live ? hn : h;
        }
    } else {
        #pragma unroll 4
        for (int s = 0; s < WU; ++s) {
            const double2 xd = xw[s];
            STEP(xd, cn, hn);
            c_ = cn;
            h  = hn;
        }
    }

    // ---- emission (clean path for every block; preload absorbed clamps) ----
    float* op = out + (size_t)(g * CL) * 4 + j;
    const double2* xe = xw + 1;                      // skew bump at s==32
    #pragma unroll 4
    for (int s = WU; s < WU + CL; ++s) {
        const double2 xd = xe[s];
        STEP(xd, cn, hn);
        c_ = cn;
        h  = hn;
        *op = h;
        op += 4;
    }
#undef STEP
}

extern "C" void kernel_launch(void* const* d_in, const int* in_sizes, int n_in,
                              void* d_out, int out_size)
{
    const float4*  x  = (const float4*)d_in[0];
    const float*  Wih = (const float*)d_in[1];
    const float*  Whh = (const float*)d_in[2];
    const float*  bih = (const float*)d_in[3];
    const float*  bhh = (const float*)d_in[4];
    const float*  h0  = (const float*)d_in[5];
    const float*  c0  = (const float*)d_in[6];
    float*        out = (float*)d_out;

    (void)in_sizes; (void)n_in; (void)out_size;

    lstm_chunked_scan<<<NTHREADS / BLOCK, BLOCK>>>(x, Wih, Whh, bih, bhh, h0, c0, out);
}